// round 8
// baseline (speedup 1.0000x reference)
#include <cuda_runtime.h>
#include <cstdint>
#include <math.h>

// Accurate libdevice log (what XLA emits for lax.log on f32): exact fallback
// paths so argmax ordering is provably identical to the reference.
extern "C" __device__ float __nv_logf(float);

// Opaque multiplier == 1, loaded from global memory. ptxas cannot prove its
// value, so mad.lo.u32 with it MUST stay IMAD (fma pipe), rebalancing the
// threefry adds off the saturated alu pipe (SHF/LOP3).
__device__ unsigned g_one = 1u;

// add via IMAD on the fma pipe: d = a*one + b  (one == 1 at runtime)
__device__ __forceinline__ unsigned addi(unsigned a, unsigned b, unsigned one) {
    unsigned d;
    asm("mad.lo.u32 %0, %1, %2, %3;" : "=r"(d) : "r"(a), "r"(one), "r"(b));
    return d;
}

// ---------------------------------------------------------------------------
// Compile-time Threefry-2x32 for split keys (partitionable fold-like split).
// ---------------------------------------------------------------------------
constexpr unsigned crotl(unsigned x, int r) { return (x << r) | (x >> (32 - r)); }
struct CKeys { unsigned a, b; };
constexpr CKeys ctf(unsigned k0, unsigned k1, unsigned x0, unsigned x1) {
    unsigned k2 = k0 ^ k1 ^ 0x1BD11BDAu;
    const int rotA[4] = {13, 15, 26, 6};
    const int rotB[4] = {17, 29, 16, 24};
    x0 += k0; x1 += k1;
    for (int i = 0; i < 4; i++) { x0 += x1; x1 = crotl(x1, rotA[i]); x1 ^= x0; }
    x0 += k1; x1 += k2 + 1u;
    for (int i = 0; i < 4; i++) { x0 += x1; x1 = crotl(x1, rotB[i]); x1 ^= x0; }
    x0 += k2; x1 += k0 + 2u;
    for (int i = 0; i < 4; i++) { x0 += x1; x1 = crotl(x1, rotA[i]); x1 ^= x0; }
    x0 += k0; x1 += k1 + 3u;
    for (int i = 0; i < 4; i++) { x0 += x1; x1 = crotl(x1, rotB[i]); x1 ^= x0; }
    x0 += k1; x1 += k2 + 4u;
    for (int i = 0; i < 4; i++) { x0 += x1; x1 = crotl(x1, rotA[i]); x1 ^= x0; }
    x0 += k2; x1 += k0 + 5u;
    return {x0, x1};
}
constexpr CKeys KCAT  = ctf(0u, 42u, 0u, 0u);   // k_cat
constexpr CKeys KBERN = ctf(0u, 42u, 0u, 1u);   // k_bern

// ---------------------------------------------------------------------------
// Device Threefry-2x32; partitionable 32-bit bits = lane0 ^ lane1, ctr (0, j).
// All integer adds forced to IMAD (fma pipe) via the opaque 'one'.
// ---------------------------------------------------------------------------
__device__ __forceinline__ unsigned rotl(unsigned x, int r) {
    return __funnelshift_l(x, x, r);
}

__device__ __forceinline__ unsigned tf_bits32(unsigned one, unsigned k0,
                                              unsigned k1, unsigned x1) {
    const unsigned k2 = k0 ^ k1 ^ 0x1BD11BDAu;
    unsigned x0 = k0;
    x1 = addi(x1, k1, one);
#define TFR(r) { x0 = addi(x0, x1, one); x1 = rotl(x1, r); x1 ^= x0; }
    TFR(13) TFR(15) TFR(26) TFR(6)
    x0 = addi(x0, k1, one); x1 = addi(x1, k2 + 1u, one);
    TFR(17) TFR(29) TFR(16) TFR(24)
    x0 = addi(x0, k2, one); x1 = addi(x1, k0 + 2u, one);
    TFR(13) TFR(15) TFR(26) TFR(6)
    x0 = addi(x0, k0, one); x1 = addi(x1, k1 + 3u, one);
    TFR(17) TFR(29) TFR(16) TFR(24)
    x0 = addi(x0, k1, one); x1 = addi(x1, k2 + 4u, one);
    TFR(13) TFR(15) TFR(26) TFR(6)
#undef TFR
    return addi(x0, k2, one) ^ addi(x1, k0 + 5u, one);
}

// JAX uniform [0,1): bitcast((bits>>9)|0x3f800000) - 1
__device__ __forceinline__ float u01f(unsigned bits) {
    return __uint_as_float((bits >> 9) | 0x3f800000u) - 1.0f;
}

#define TINY   1.17549435e-38f
#define T_MIN  0.001953125f   /* below this t, MUFU log(u) rel-err too big -> exact fix */
#define GAPTHR 1e-3f          /* >> max cheap-score error (~2e-4); proven R5 */

// (value, index) max with exact second-max propagation; ties -> lower index
struct TopK { float v1; float v2; int i1; };
__device__ __forceinline__ TopK tk_merge(TopK a, TopK b) {
    TopK r;
    if (b.v1 > a.v1) { r.v1 = b.v1; r.i1 = b.i1; r.v2 = fmaxf(a.v1, b.v2); }
    else             { r.v1 = a.v1; r.i1 = a.i1; r.v2 = fmaxf(b.v1, a.v2); }
    return r;
}

// ---------------------------------------------------------------------------
// One thread per 8x8 window. Phase-split threefry (8 chains live), tournament
// top-2, 4-way esum. Cheap __logf scores with top-2 gap screen + rare exact
// fallback. All threefry adds pinned to the fma pipe via IMAD.
// ---------------------------------------------------------------------------
__global__ __launch_bounds__(128)
void keypoint_sampler_kernel(const float* __restrict__ x, float* __restrict__ out) {
    const unsigned one = g_one;                          // opaque 1 (runtime)
    const unsigned w = blockIdx.x * 128u + threadIdx.x;  // 0 .. 524287

    const unsigned b  = w >> 16;
    const unsigned hc = (w >> 8) & 255u;
    const unsigned wc = w & 255u;

    const float* base = x + ((size_t)b << 22) + (size_t)(hc * 8u) * 2048u + wc * 8u;

    // Bernoulli bits early (independent ILP across the whole mainloop)
    const unsigned bbits = tf_bits32(one, KBERN.a, KBERN.b, w);

    TopK top; top.v1 = -3.4e38f; top.v2 = -3.4e38f; top.i1 = 0;
    float es0 = 0.f, es1 = 0.f, es2 = 0.f, es3 = 0.f;

    const unsigned cbase = w * 64u;

#pragma unroll 1
    for (int r = 0; r < 8; r++) {
        const float4 p0 = *(const float4*)(base + (size_t)r * 2048u);
        const float4 p1 = *(const float4*)(base + (size_t)r * 2048u + 4u);
        float v[8] = {p0.x, p0.y, p0.z, p0.w, p1.x, p1.y, p1.z, p1.w};

        const unsigned c = cbase + (unsigned)r * 8u;

        // Phase 1: 8 independent threefry chains in flight
        unsigned g[8];
#pragma unroll
        for (int i = 0; i < 8; i++)
            g[i] = tf_bits32(one, KCAT.a, KCAT.b, c + (unsigned)i);

        // Phase 2: 8 independent score pipelines (MUFU latency overlapped)
        float s[8];
#pragma unroll
        for (int i = 0; i < 8; i++) {
            const float u = fmaxf(u01f(g[i]), TINY);
            float t = -__logf(u);
            if (t < T_MIN) t = -__nv_logf(u);   // rare near-u=1 exact fix
            s[i] = v[i] - __logf(t);
        }
        es0 += __expf(v[0]) + __expf(v[4]);
        es1 += __expf(v[1]) + __expf(v[5]);
        es2 += __expf(v[2]) + __expf(v[6]);
        es3 += __expf(v[3]) + __expf(v[7]);

        // Tournament top-2 within the row (depth 3), ties -> lower index
        TopK t01, t23, t45, t67, ta, tb, row;
        t01.v1 = (s[1] > s[0]) ? s[1] : s[0];
        t01.i1 = (s[1] > s[0]) ? r*8+1 : r*8+0;
        t01.v2 = fminf(s[0], s[1]);
        t23.v1 = (s[3] > s[2]) ? s[3] : s[2];
        t23.i1 = (s[3] > s[2]) ? r*8+3 : r*8+2;
        t23.v2 = fminf(s[2], s[3]);
        t45.v1 = (s[5] > s[4]) ? s[5] : s[4];
        t45.i1 = (s[5] > s[4]) ? r*8+5 : r*8+4;
        t45.v2 = fminf(s[4], s[5]);
        t67.v1 = (s[7] > s[6]) ? s[7] : s[6];
        t67.i1 = (s[7] > s[6]) ? r*8+7 : r*8+6;
        t67.v2 = fminf(s[6], s[7]);
        ta  = tk_merge(t01, t23);
        tb  = tk_merge(t45, t67);
        row = tk_merge(ta, tb);
        top = tk_merge(top, row);
    }

    int bi = top.i1;

    // Ambiguous top-2 (P ~ 1e-3): redo window bitwise-exact.
    if (top.v1 - top.v2 < GAPTHR) {
        float best = -3.4e38f; bi = 0;
#pragma unroll 1
        for (int r = 0; r < 8; r++) {
#pragma unroll 1
            for (int i = 0; i < 8; i++) {
                const unsigned gb = tf_bits32(one, KCAT.a, KCAT.b,
                                              cbase + (unsigned)(r * 8 + i));
                const float uu = fmaxf(u01f(gb), TINY);
                const float tt = -__nv_logf(uu);
                const float s = __ldg(base + (size_t)r * 2048u + (unsigned)i)
                                - __nv_logf(tt);
                if (s > best) { best = s; bi = r * 8 + i; }
            }
        }
    }

    const float esum = (es0 + es1) + (es2 + es3);

    // Selected grid value via one cached load
    const float sel = __ldg(base + (size_t)(bi >> 3) * 2048u + (unsigned)(bi & 7));

    const float u = u01f(bbits);

    // Fast f32 sigmoid; double path only inside the 2e-3 boundary band.
    const float e    = __expf(-fabsf(sel));
    const float rr   = __fdividef(1.0f, 1.0f + e);
    const float sigf = (sel >= 0.0f) ? rr : 1.0f - rr;
    const float du   = u - sigf;
    bool acc;
    if (fabsf(du) > 2e-3f) {
        acc = du < 0.0f;
    } else {
        const double sig = 1.0 / (1.0 + exp(-(double)sel));
        acc = u < (float)sig;
    }

    const float lse     = log1pf(e);
    const float bern_lp = (acc ? fminf(sel, 0.0f) : fminf(-sel, 0.0f)) - lse;
    const float cat_lp  = sel - __logf(esum);   // abs err ~2e-6, tol 1e-3

    const int ddi = bi >> 3, ddj = bi & 7;

    // tuple layout: kp_xy [2*524288] | log_probs [524288] | mask [524288]
    ((float2*)out)[w]  = make_float2((float)(wc * 8u + (unsigned)ddj),   // x
                                     (float)(hc * 8u + (unsigned)ddi)); // y
    out[1048576u + w]  = cat_lp + bern_lp;
    out[1572864u + w]  = acc ? 1.0f : 0.0f;
}

extern "C" void kernel_launch(void* const* d_in, const int* in_sizes, int n_in,
                              void* d_out, int out_size) {
    const float* x = (const float*)d_in[0];
    float* out = (float*)d_out;
    keypoint_sampler_kernel<<<4096, 128>>>(x, out);
}

// round 9
// speedup vs baseline: 1.0652x; 1.0652x over previous
#include <cuda_runtime.h>
#include <cstdint>
#include <math.h>

// Accurate libdevice log (what XLA emits for lax.log on f32): exact fallback
// paths so argmax ordering is provably identical to the reference.
extern "C" __device__ float __nv_logf(float);

// Opaque multiplier == 1, loaded once per block (uniform). Only the 20
// reg-reg round adds per threefry use it, so the cost is ~1 register; the
// immediate key-injection adds stay as IADD3-with-immediate on the alu pipe.
__device__ unsigned g_one = 1u;

// x0 = x1*one + x0  -> IMAD on the fma pipe (ptxas cannot prove one==1)
__device__ __forceinline__ unsigned madd(unsigned acc, unsigned addend, unsigned one) {
    unsigned d;
    asm("mad.lo.u32 %0, %1, %2, %3;" : "=r"(d) : "r"(addend), "r"(one), "r"(acc));
    return d;
}

// ---------------------------------------------------------------------------
// Compile-time Threefry-2x32 for split keys (partitionable fold-like split).
// ---------------------------------------------------------------------------
constexpr unsigned crotl(unsigned x, int r) { return (x << r) | (x >> (32 - r)); }
struct CKeys { unsigned a, b; };
constexpr CKeys ctf(unsigned k0, unsigned k1, unsigned x0, unsigned x1) {
    unsigned k2 = k0 ^ k1 ^ 0x1BD11BDAu;
    const int rotA[4] = {13, 15, 26, 6};
    const int rotB[4] = {17, 29, 16, 24};
    x0 += k0; x1 += k1;
    for (int i = 0; i < 4; i++) { x0 += x1; x1 = crotl(x1, rotA[i]); x1 ^= x0; }
    x0 += k1; x1 += k2 + 1u;
    for (int i = 0; i < 4; i++) { x0 += x1; x1 = crotl(x1, rotB[i]); x1 ^= x0; }
    x0 += k2; x1 += k0 + 2u;
    for (int i = 0; i < 4; i++) { x0 += x1; x1 = crotl(x1, rotA[i]); x1 ^= x0; }
    x0 += k0; x1 += k1 + 3u;
    for (int i = 0; i < 4; i++) { x0 += x1; x1 = crotl(x1, rotB[i]); x1 ^= x0; }
    x0 += k1; x1 += k2 + 4u;
    for (int i = 0; i < 4; i++) { x0 += x1; x1 = crotl(x1, rotA[i]); x1 ^= x0; }
    x0 += k2; x1 += k0 + 5u;
    return {x0, x1};
}
constexpr CKeys KCAT  = ctf(0u, 42u, 0u, 0u);   // k_cat
constexpr CKeys KBERN = ctf(0u, 42u, 0u, 1u);   // k_bern

// ---------------------------------------------------------------------------
// Device Threefry-2x32; partitionable 32-bit bits = lane0 ^ lane1, ctr (0, j).
// Round adds (reg-reg) forced to IMAD/fma pipe; key injections stay IADD3-imm.
// ---------------------------------------------------------------------------
__device__ __forceinline__ unsigned rotl(unsigned x, int r) {
    return __funnelshift_l(x, x, r);
}

__device__ __forceinline__ unsigned tf_bits32(unsigned one, unsigned k0,
                                              unsigned k1, unsigned x1) {
    const unsigned k2 = k0 ^ k1 ^ 0x1BD11BDAu;
    unsigned x0 = k0;
    x1 += k1;
#define TFR(r) { x0 = madd(x0, x1, one); x1 = rotl(x1, r); x1 ^= x0; }
    TFR(13) TFR(15) TFR(26) TFR(6)
    x0 += k1; x1 += k2 + 1u;
    TFR(17) TFR(29) TFR(16) TFR(24)
    x0 += k2; x1 += k0 + 2u;
    TFR(13) TFR(15) TFR(26) TFR(6)
    x0 += k0; x1 += k1 + 3u;
    TFR(17) TFR(29) TFR(16) TFR(24)
    x0 += k1; x1 += k2 + 4u;
    TFR(13) TFR(15) TFR(26) TFR(6)
#undef TFR
    return (x0 + k2) ^ (x1 + k0 + 5u);
}

// JAX uniform [0,1): bitcast((bits>>9)|0x3f800000) - 1
__device__ __forceinline__ float u01f(unsigned bits) {
    return __uint_as_float((bits >> 9) | 0x3f800000u) - 1.0f;
}

#define TINY   1.17549435e-38f
#define T_MIN  0.001953125f   /* below this t, MUFU log(u) rel-err too big -> exact fix */
#define GAPTHR 1e-3f          /* >> max cheap-score error (~2e-4); proven R5 */

// (value, index) max with exact second-max propagation; ties -> lower index
struct TopK { float v1; float v2; int i1; };
__device__ __forceinline__ TopK tk_merge(TopK a, TopK b) {
    TopK r;
    if (b.v1 > a.v1) { r.v1 = b.v1; r.i1 = b.i1; r.v2 = fmaxf(a.v1, b.v2); }
    else             { r.v1 = a.v1; r.i1 = a.i1; r.v2 = fmaxf(b.v1, a.v2); }
    return r;
}

// ---------------------------------------------------------------------------
// One thread per 8x8 window. Phase-split threefry (8 chains live), tournament
// top-2, 4-way esum. Cheap __logf scores with top-2 gap screen + rare exact
// fallback. Threefry round adds pinned to the fma pipe.
// ---------------------------------------------------------------------------
__global__ __launch_bounds__(128)
void keypoint_sampler_kernel(const float* __restrict__ x, float* __restrict__ out) {
    const unsigned one = g_one;                          // opaque 1 (uniform)
    const unsigned w = blockIdx.x * 128u + threadIdx.x;  // 0 .. 524287

    const unsigned b  = w >> 16;
    const unsigned hc = (w >> 8) & 255u;
    const unsigned wc = w & 255u;

    const float* base = x + ((size_t)b << 22) + (size_t)(hc * 8u) * 2048u + wc * 8u;

    // Bernoulli bits early (independent ILP across the whole mainloop)
    const unsigned bbits = tf_bits32(one, KBERN.a, KBERN.b, w);

    TopK top; top.v1 = -3.4e38f; top.v2 = -3.4e38f; top.i1 = 0;
    float es0 = 0.f, es1 = 0.f, es2 = 0.f, es3 = 0.f;

    const unsigned cbase = w * 64u;

#pragma unroll 1
    for (int r = 0; r < 8; r++) {
        const float4 p0 = *(const float4*)(base + (size_t)r * 2048u);
        const float4 p1 = *(const float4*)(base + (size_t)r * 2048u + 4u);
        float v[8] = {p0.x, p0.y, p0.z, p0.w, p1.x, p1.y, p1.z, p1.w};

        const unsigned c = cbase + (unsigned)r * 8u;

        // Phase 1: 8 independent threefry chains in flight
        unsigned g[8];
#pragma unroll
        for (int i = 0; i < 8; i++)
            g[i] = tf_bits32(one, KCAT.a, KCAT.b, c + (unsigned)i);

        // Phase 2: 8 independent score pipelines (MUFU latency overlapped)
        float s[8];
#pragma unroll
        for (int i = 0; i < 8; i++) {
            const float u = fmaxf(u01f(g[i]), TINY);
            float t = -__logf(u);
            if (t < T_MIN) t = -__nv_logf(u);   // rare near-u=1 exact fix
            s[i] = v[i] - __logf(t);
        }
        es0 += __expf(v[0]) + __expf(v[4]);
        es1 += __expf(v[1]) + __expf(v[5]);
        es2 += __expf(v[2]) + __expf(v[6]);
        es3 += __expf(v[3]) + __expf(v[7]);

        // Tournament top-2 within the row (depth 3), ties -> lower index
        TopK t01, t23, t45, t67, ta, tb, row;
        t01.v1 = (s[1] > s[0]) ? s[1] : s[0];
        t01.i1 = (s[1] > s[0]) ? r*8+1 : r*8+0;
        t01.v2 = fminf(s[0], s[1]);
        t23.v1 = (s[3] > s[2]) ? s[3] : s[2];
        t23.i1 = (s[3] > s[2]) ? r*8+3 : r*8+2;
        t23.v2 = fminf(s[2], s[3]);
        t45.v1 = (s[5] > s[4]) ? s[5] : s[4];
        t45.i1 = (s[5] > s[4]) ? r*8+5 : r*8+4;
        t45.v2 = fminf(s[4], s[5]);
        t67.v1 = (s[7] > s[6]) ? s[7] : s[6];
        t67.i1 = (s[7] > s[6]) ? r*8+7 : r*8+6;
        t67.v2 = fminf(s[6], s[7]);
        ta  = tk_merge(t01, t23);
        tb  = tk_merge(t45, t67);
        row = tk_merge(ta, tb);
        top = tk_merge(top, row);
    }

    int bi = top.i1;

    // Ambiguous top-2 (P ~ 1e-3): redo window bitwise-exact.
    if (top.v1 - top.v2 < GAPTHR) {
        float best = -3.4e38f; bi = 0;
#pragma unroll 1
        for (int r = 0; r < 8; r++) {
#pragma unroll 1
            for (int i = 0; i < 8; i++) {
                const unsigned gb = tf_bits32(one, KCAT.a, KCAT.b,
                                              cbase + (unsigned)(r * 8 + i));
                const float uu = fmaxf(u01f(gb), TINY);
                const float tt = -__nv_logf(uu);
                const float s = __ldg(base + (size_t)r * 2048u + (unsigned)i)
                                - __nv_logf(tt);
                if (s > best) { best = s; bi = r * 8 + i; }
            }
        }
    }

    const float esum = (es0 + es1) + (es2 + es3);

    // Selected grid value via one cached load
    const float sel = __ldg(base + (size_t)(bi >> 3) * 2048u + (unsigned)(bi & 7));

    const float u = u01f(bbits);

    // Fast f32 sigmoid; double path only inside the 2e-3 boundary band.
    const float e    = __expf(-fabsf(sel));
    const float rr   = __fdividef(1.0f, 1.0f + e);
    const float sigf = (sel >= 0.0f) ? rr : 1.0f - rr;
    const float du   = u - sigf;
    bool acc;
    if (fabsf(du) > 2e-3f) {
        acc = du < 0.0f;
    } else {
        const double sig = 1.0 / (1.0 + exp(-(double)sel));
        acc = u < (float)sig;
    }

    const float lse     = log1pf(e);
    const float bern_lp = (acc ? fminf(sel, 0.0f) : fminf(-sel, 0.0f)) - lse;
    const float cat_lp  = sel - __logf(esum);   // abs err ~2e-6, tol 1e-3

    const int ddi = bi >> 3, ddj = bi & 7;

    // tuple layout: kp_xy [2*524288] | log_probs [524288] | mask [524288]
    ((float2*)out)[w]  = make_float2((float)(wc * 8u + (unsigned)ddj),   // x
                                     (float)(hc * 8u + (unsigned)ddi)); // y
    out[1048576u + w]  = cat_lp + bern_lp;
    out[1572864u + w]  = acc ? 1.0f : 0.0f;
}

extern "C" void kernel_launch(void* const* d_in, const int* in_sizes, int n_in,
                              void* d_out, int out_size) {
    const float* x = (const float*)d_in[0];
    float* out = (float*)d_out;
    keypoint_sampler_kernel<<<4096, 128>>>(x, out);
}

// round 10
// speedup vs baseline: 1.1669x; 1.0955x over previous
#include <cuda_runtime.h>
#include <cstdint>
#include <math.h>

// Accurate libdevice log — used ONLY in the rare exact-fallback path so the
// argmax ordering is provably identical to the XLA reference.
extern "C" __device__ float __nv_logf(float);

// ---------------------------------------------------------------------------
// Compile-time Threefry-2x32 for split keys (partitionable fold-like split).
// ---------------------------------------------------------------------------
constexpr unsigned crotl(unsigned x, int r) { return (x << r) | (x >> (32 - r)); }
struct CKeys { unsigned a, b; };
constexpr CKeys ctf(unsigned k0, unsigned k1, unsigned x0, unsigned x1) {
    unsigned k2 = k0 ^ k1 ^ 0x1BD11BDAu;
    const int rotA[4] = {13, 15, 26, 6};
    const int rotB[4] = {17, 29, 16, 24};
    x0 += k0; x1 += k1;
    for (int i = 0; i < 4; i++) { x0 += x1; x1 = crotl(x1, rotA[i]); x1 ^= x0; }
    x0 += k1; x1 += k2 + 1u;
    for (int i = 0; i < 4; i++) { x0 += x1; x1 = crotl(x1, rotB[i]); x1 ^= x0; }
    x0 += k2; x1 += k0 + 2u;
    for (int i = 0; i < 4; i++) { x0 += x1; x1 = crotl(x1, rotA[i]); x1 ^= x0; }
    x0 += k0; x1 += k1 + 3u;
    for (int i = 0; i < 4; i++) { x0 += x1; x1 = crotl(x1, rotB[i]); x1 ^= x0; }
    x0 += k1; x1 += k2 + 4u;
    for (int i = 0; i < 4; i++) { x0 += x1; x1 = crotl(x1, rotA[i]); x1 ^= x0; }
    x0 += k2; x1 += k0 + 5u;
    return {x0, x1};
}
constexpr CKeys KCAT  = ctf(0u, 42u, 0u, 0u);   // k_cat
constexpr CKeys KBERN = ctf(0u, 42u, 0u, 1u);   // k_bern

// ---------------------------------------------------------------------------
// Device Threefry-2x32; partitionable 32-bit bits = lane0 ^ lane1, ctr (0, j).
// x1p must be ctr + k1 (pre-added by the caller, folds into addressing math).
// ---------------------------------------------------------------------------
__device__ __forceinline__ unsigned rotl(unsigned x, int r) {
    return __funnelshift_l(x, x, r);
}

__device__ __forceinline__ unsigned tf_bits32p(unsigned k0, unsigned k1, unsigned x1) {
    const unsigned k2 = k0 ^ k1 ^ 0x1BD11BDAu;
    unsigned x0 = k0;
#define TFR(r) { x0 += x1; x1 = rotl(x1, r); x1 ^= x0; }
    TFR(13) TFR(15) TFR(26) TFR(6)
    x0 += k1; x1 += k2 + 1u;
    TFR(17) TFR(29) TFR(16) TFR(24)
    x0 += k2; x1 += k0 + 2u;
    TFR(13) TFR(15) TFR(26) TFR(6)
    x0 += k0; x1 += k1 + 3u;
    TFR(17) TFR(29) TFR(16) TFR(24)
    x0 += k1; x1 += k2 + 4u;
    TFR(13) TFR(15) TFR(26) TFR(6)
#undef TFR
    return (x0 + k2) ^ (x1 + k0 + 5u);
}

// JAX uniform [0,1): bitcast((bits>>9)|0x3f800000) - 1
__device__ __forceinline__ float u01f(unsigned bits) {
    return __uint_as_float((bits >> 9) | 0x3f800000u) - 1.0f;
}

#define TINY    1.17549435e-38f
#define L2E     1.44269504088896340736f   /* 1/ln2 */
#define L2EH    0.72134752044448170368f   /* 1/(2 ln2) */
#define D_SER   0.001953125f              /* d <= 2^-9: use series for -lg2(u) */
#define GAPTHR2 7.5e-4f                   /* s2-units; >=2x worst screen error */

// (value, index) max with exact second-max propagation; ties -> lower index
struct TopK { float v1; float v2; int i1; };
__device__ __forceinline__ TopK tk_merge(TopK a, TopK b) {
    TopK r;
    if (b.v1 > a.v1) { r.v1 = b.v1; r.i1 = b.i1; r.v2 = fmaxf(a.v1, b.v2); }
    else             { r.v1 = a.v1; r.i1 = a.i1; r.v2 = fmaxf(b.v1, a.v2); }
    return r;
}

// ---------------------------------------------------------------------------
// One thread per 8x8 window. Phase-split threefry (8 chains live).
// Cheap score in log2 domain: s2 = v*log2e - lg2(t2), t2 = -lg2(u) with a
// branch-free FFMA series when u is near 1 (the MUFU-degenerate region).
// p = v*log2e is shared with the EX2-based esum. Tournament top-2; exact
// window redo when the gap < GAPTHR2 or any u == 0 (minu guard).
// ---------------------------------------------------------------------------
__global__ __launch_bounds__(128)
void keypoint_sampler_kernel(const float* __restrict__ x, float* __restrict__ out) {
    const unsigned w = blockIdx.x * 128u + threadIdx.x;   // 0 .. 524287

    const unsigned b  = w >> 16;
    const unsigned hc = (w >> 8) & 255u;
    const unsigned wc = w & 255u;

    const float* base = x + ((size_t)b << 22) + (size_t)(hc * 8u) * 2048u + wc * 8u;

    // Bernoulli bits early (independent ILP across the whole mainloop)
    const unsigned bbits = tf_bits32p(KBERN.a, KBERN.b, w + KBERN.b);

    TopK top; top.v1 = -3.4e38f; top.v2 = -3.4e38f; top.i1 = 0;
    float es0 = 0.f, es1 = 0.f, es2 = 0.f, es3 = 0.f;
    float minu = 1.0f;

    const unsigned cbase = w * 64u;

#pragma unroll 1
    for (int r = 0; r < 8; r++) {
        const float4 p0 = *(const float4*)(base + (size_t)r * 2048u);
        const float4 p1 = *(const float4*)(base + (size_t)r * 2048u + 4u);
        float v[8] = {p0.x, p0.y, p0.z, p0.w, p1.x, p1.y, p1.z, p1.w};

        const unsigned ckr = cbase + (unsigned)r * 8u + KCAT.b;  // ctr + k1

        // Phase 1: 8 independent threefry chains in flight
        unsigned g[8];
#pragma unroll
        for (int i = 0; i < 8; i++)
            g[i] = tf_bits32p(KCAT.a, KCAT.b, ckr + (unsigned)i);

        // Phase 2: 8 independent score pipelines, branch-free
        float s[8];
#pragma unroll
        for (int i = 0; i < 8; i++) {
            const float u = u01f(g[i]);
            minu = fminf(minu, u);
            const float d   = 1.0f - u;
            const float t2m = -__log2f(u);                       // MUFU path
            const float t2f = d * fmaf(d, L2EH, L2E);            // series path
            const float t2  = (d < D_SER) ? t2f : t2m;
            const float p   = v[i] * L2E;
            s[i] = p - __log2f(t2);                              // score (s/ln2 + C)
            const float ev = exp2f(p);                           // == expf(v)
            if ((i & 3) == 0) es0 += ev;
            else if ((i & 3) == 1) es1 += ev;
            else if ((i & 3) == 2) es2 += ev;
            else es3 += ev;
        }

        // Tournament top-2 within the row (depth 3), ties -> lower index
        TopK t01, t23, t45, t67, ta, tb, row;
        t01.v1 = (s[1] > s[0]) ? s[1] : s[0];
        t01.i1 = (s[1] > s[0]) ? r*8+1 : r*8+0;
        t01.v2 = fminf(s[0], s[1]);
        t23.v1 = (s[3] > s[2]) ? s[3] : s[2];
        t23.i1 = (s[3] > s[2]) ? r*8+3 : r*8+2;
        t23.v2 = fminf(s[2], s[3]);
        t45.v1 = (s[5] > s[4]) ? s[5] : s[4];
        t45.i1 = (s[5] > s[4]) ? r*8+5 : r*8+4;
        t45.v2 = fminf(s[4], s[5]);
        t67.v1 = (s[7] > s[6]) ? s[7] : s[6];
        t67.i1 = (s[7] > s[6]) ? r*8+7 : r*8+6;
        t67.v2 = fminf(s[6], s[7]);
        ta  = tk_merge(t01, t23);
        tb  = tk_merge(t45, t67);
        row = tk_merge(ta, tb);
        top = tk_merge(top, row);
    }

    int bi = top.i1;

    // Ambiguous top-2 (P ~ 1e-3) or a u==0 slot: redo window bitwise-exact.
    if ((top.v1 - top.v2 < GAPTHR2) || (minu <= 0.0f)) {
        float best = -3.4e38f; bi = 0;
#pragma unroll 1
        for (int r = 0; r < 8; r++) {
#pragma unroll 1
            for (int i = 0; i < 8; i++) {
                const unsigned gb = tf_bits32p(KCAT.a, KCAT.b,
                                               cbase + (unsigned)(r * 8 + i) + KCAT.b);
                const float uu = fmaxf(u01f(gb), TINY);
                const float tt = -__nv_logf(uu);
                const float s = __ldg(base + (size_t)r * 2048u + (unsigned)i)
                                - __nv_logf(tt);
                if (s > best) { best = s; bi = r * 8 + i; }
            }
        }
    }

    const float esum = (es0 + es1) + (es2 + es3);

    // Selected grid value via one cached load
    const float sel = __ldg(base + (size_t)(bi >> 3) * 2048u + (unsigned)(bi & 7));

    const float u = u01f(bbits);

    // Fast f32 sigmoid; double path only inside the 2e-3 boundary band.
    const float e    = __expf(-fabsf(sel));
    const float rr   = __fdividef(1.0f, 1.0f + e);
    const float sigf = (sel >= 0.0f) ? rr : 1.0f - rr;
    const float du   = u - sigf;
    bool acc;
    if (fabsf(du) > 2e-3f) {
        acc = du < 0.0f;
    } else {
        const double sig = 1.0 / (1.0 + exp(-(double)sel));
        acc = u < (float)sig;
    }

    const float lse     = log1pf(e);
    const float bern_lp = (acc ? fminf(sel, 0.0f) : fminf(-sel, 0.0f)) - lse;
    const float cat_lp  = sel - __logf(esum);   // abs err ~2e-6, tol 1e-3

    const int ddi = bi >> 3, ddj = bi & 7;

    // tuple layout: kp_xy [2*524288] | log_probs [524288] | mask [524288]
    ((float2*)out)[w]  = make_float2((float)(wc * 8u + (unsigned)ddj),   // x
                                     (float)(hc * 8u + (unsigned)ddi)); // y
    out[1048576u + w]  = cat_lp + bern_lp;
    out[1572864u + w]  = acc ? 1.0f : 0.0f;
}

extern "C" void kernel_launch(void* const* d_in, const int* in_sizes, int n_in,
                              void* d_out, int out_size) {
    const float* x = (const float*)d_in[0];
    float* out = (float*)d_out;
    keypoint_sampler_kernel<<<4096, 128>>>(x, out);
}